// round 1
// baseline (speedup 1.0000x reference)
#include <cuda_runtime.h>

#define BB 8
#define SS 2048
#define FF 1024
#define NEGV -1000000000.0f

// Scratch (allocation-free rule: __device__ globals)
__device__ float g_Q[BB * SS * FF];   // 64 MB
__device__ float g_K[BB * SS * FF];   // 64 MB
__device__ float g_V[BB * SS * FF];   // 64 MB
__device__ float g_P[BB * SS * SS];   // 128 MB (scores -> probs in place)

// ---------------------------------------------------------------------------
// Tiled 64x64x16 fp32 GEMM building blocks. 256 threads, 4x4 micro-tile.
// NT form: C[m,n] = sum_k A[m,k] * Bm[n,k]   (both operands K-contiguous)
// NN form: C[m,n] = sum_k A[m,k] * Bm[k,n]
// ---------------------------------------------------------------------------

// Kernel 1: QKV projection. z selects (W, bias, dst). A = x [16384, 1024].
__global__ void __launch_bounds__(256) qkv_kernel(
    const float* __restrict__ x,
    const float* __restrict__ Wq, const float* __restrict__ bq,
    const float* __restrict__ Wk, const float* __restrict__ bk,
    const float* __restrict__ Wv, const float* __restrict__ bv)
{
    const float* W; const float* bias; float* C;
    if (blockIdx.z == 0)      { W = Wq; bias = bq; C = g_Q; }
    else if (blockIdx.z == 1) { W = Wk; bias = bk; C = g_K; }
    else                      { W = Wv; bias = bv; C = g_V; }

    const int m0 = blockIdx.y * 64;
    const int n0 = blockIdx.x * 64;

    __shared__ float As[16][64];
    __shared__ float Bs[16][64];

    const int tid = threadIdx.x;
    const int lr = tid >> 2;          // 0..63 (tile row)
    const int lc = (tid & 3) * 4;     // 0,4,8,12 (k offset)
    const int ty = tid >> 4;          // 0..15 (M dir)
    const int tx = tid & 15;          // 0..15 (N dir)

    float acc[4][4] = {};

    for (int k0 = 0; k0 < FF; k0 += 16) {
        float4 a = *(const float4*)&x[(size_t)(m0 + lr) * FF + k0 + lc];
        float4 w = *(const float4*)&W[(size_t)(n0 + lr) * FF + k0 + lc];
        As[lc + 0][lr] = a.x; As[lc + 1][lr] = a.y;
        As[lc + 2][lr] = a.z; As[lc + 3][lr] = a.w;
        Bs[lc + 0][lr] = w.x; Bs[lc + 1][lr] = w.y;
        Bs[lc + 2][lr] = w.z; Bs[lc + 3][lr] = w.w;
        __syncthreads();
        #pragma unroll
        for (int k = 0; k < 16; ++k) {
            float4 af = *(const float4*)&As[k][ty * 4];
            float4 bf = *(const float4*)&Bs[k][tx * 4];
            acc[0][0] += af.x * bf.x; acc[0][1] += af.x * bf.y;
            acc[0][2] += af.x * bf.z; acc[0][3] += af.x * bf.w;
            acc[1][0] += af.y * bf.x; acc[1][1] += af.y * bf.y;
            acc[1][2] += af.y * bf.z; acc[1][3] += af.y * bf.w;
            acc[2][0] += af.z * bf.x; acc[2][1] += af.z * bf.y;
            acc[2][2] += af.z * bf.z; acc[2][3] += af.z * bf.w;
            acc[3][0] += af.w * bf.x; acc[3][1] += af.w * bf.y;
            acc[3][2] += af.w * bf.z; acc[3][3] += af.w * bf.w;
        }
        __syncthreads();
    }

    float4 bv4 = *(const float4*)&bias[n0 + tx * 4];
    #pragma unroll
    for (int i = 0; i < 4; ++i) {
        float4 o;
        o.x = acc[i][0] + bv4.x; o.y = acc[i][1] + bv4.y;
        o.z = acc[i][2] + bv4.z; o.w = acc[i][3] + bv4.w;
        *(float4*)&C[(size_t)(m0 + ty * 4 + i) * FF + n0 + tx * 4] = o;
    }
}

// Kernel 2: scores = scale * Q @ K^T with causal + padding mask fused.
// Skips tiles strictly above the diagonal (never written, never read later).
__global__ void __launch_bounds__(256) scores_kernel(const int* __restrict__ pad_mask)
{
    const int b  = blockIdx.z;
    const int qt = blockIdx.y;
    const int kt = blockIdx.x;
    if (kt > qt) return;

    const float* A  = g_Q + (size_t)b * SS * FF;
    const float* Bm = g_K + (size_t)b * SS * FF;
    float*       C  = g_P + (size_t)b * SS * SS;

    const int m0 = qt * 64;
    const int n0 = kt * 64;

    __shared__ float As[16][64];
    __shared__ float Bs[16][64];

    const int tid = threadIdx.x;
    const int lr = tid >> 2;
    const int lc = (tid & 3) * 4;
    const int ty = tid >> 4;
    const int tx = tid & 15;

    float acc[4][4] = {};

    for (int k0 = 0; k0 < FF; k0 += 16) {
        float4 a = *(const float4*)&A [(size_t)(m0 + lr) * FF + k0 + lc];
        float4 w = *(const float4*)&Bm[(size_t)(n0 + lr) * FF + k0 + lc];
        As[lc + 0][lr] = a.x; As[lc + 1][lr] = a.y;
        As[lc + 2][lr] = a.z; As[lc + 3][lr] = a.w;
        Bs[lc + 0][lr] = w.x; Bs[lc + 1][lr] = w.y;
        Bs[lc + 2][lr] = w.z; Bs[lc + 3][lr] = w.w;
        __syncthreads();
        #pragma unroll
        for (int k = 0; k < 16; ++k) {
            float4 af = *(const float4*)&As[k][ty * 4];
            float4 bf = *(const float4*)&Bs[k][tx * 4];
            acc[0][0] += af.x * bf.x; acc[0][1] += af.x * bf.y;
            acc[0][2] += af.x * bf.z; acc[0][3] += af.x * bf.w;
            acc[1][0] += af.y * bf.x; acc[1][1] += af.y * bf.y;
            acc[1][2] += af.y * bf.z; acc[1][3] += af.y * bf.w;
            acc[2][0] += af.z * bf.x; acc[2][1] += af.z * bf.y;
            acc[2][2] += af.z * bf.z; acc[2][3] += af.z * bf.w;
            acc[3][0] += af.w * bf.x; acc[3][1] += af.w * bf.y;
            acc[3][2] += af.w * bf.z; acc[3][3] += af.w * bf.w;
        }
        __syncthreads();
    }

    const float scale = 0.03125f;  // 1/sqrt(1024)
    int4 pm = *(const int4*)&pad_mask[(size_t)b * SS + n0 + tx * 4];
    #pragma unroll
    for (int i = 0; i < 4; ++i) {
        int q = m0 + ty * 4 + i;
        int kcol = n0 + tx * 4;
        float4 o;
        o.x = (pm.x == 0 || (kcol + 0) > q) ? NEGV : acc[i][0] * scale;
        o.y = (pm.y == 0 || (kcol + 1) > q) ? NEGV : acc[i][1] * scale;
        o.z = (pm.z == 0 || (kcol + 2) > q) ? NEGV : acc[i][2] * scale;
        o.w = (pm.w == 0 || (kcol + 3) > q) ? NEGV : acc[i][3] * scale;
        *(float4*)&C[(size_t)q * SS + kcol] = o;
    }
}

// Kernel 3: row softmax over k in [0, q], zero-fill to diagonal-tile boundary.
__global__ void __launch_bounds__(256) softmax_kernel()
{
    const int b = blockIdx.y;
    const int q = blockIdx.x;
    float* row = g_P + (size_t)b * SS * SS + (size_t)q * SS;
    const int len = q + 1;
    const int tid = threadIdx.x;

    __shared__ float red[32];

    float vals[8];
    float m = -3.4e38f;
    #pragma unroll
    for (int i = 0; i < 8; ++i) {
        int k = tid + i * 256;
        vals[i] = (k < len) ? row[k] : -3.4e38f;
        m = fmaxf(m, vals[i]);
    }
    // block max
    #pragma unroll
    for (int o = 16; o > 0; o >>= 1) m = fmaxf(m, __shfl_xor_sync(0xffffffffu, m, o));
    if ((tid & 31) == 0) red[tid >> 5] = m;
    __syncthreads();
    m = red[tid & 7];
    #pragma unroll
    for (int o = 4; o > 0; o >>= 1) m = fmaxf(m, __shfl_xor_sync(0xffffffffu, m, o));
    __syncthreads();

    float s = 0.f;
    #pragma unroll
    for (int i = 0; i < 8; ++i) {
        vals[i] = __expf(vals[i] - m);
        s += vals[i];
    }
    #pragma unroll
    for (int o = 16; o > 0; o >>= 1) s += __shfl_xor_sync(0xffffffffu, s, o);
    if ((tid & 31) == 0) red[tid >> 5] = s;
    __syncthreads();
    s = red[tid & 7];
    #pragma unroll
    for (int o = 4; o > 0; o >>= 1) s += __shfl_xor_sync(0xffffffffu, s, o);

    const float inv = 1.0f / s;
    #pragma unroll
    for (int i = 0; i < 8; ++i) {
        int k = tid + i * 256;
        if (k < len) row[k] = vals[i] * inv;
    }
    // zero-fill remainder of the diagonal 64-tile so AV can read whole tiles
    const int kEnd = ((q >> 6) + 1) << 6;
    for (int k = len + tid; k < kEnd; k += 256) row[k] = 0.f;
}

// Kernel 4: out = P @ V (NN), k-loop truncated at the causal boundary.
__global__ void __launch_bounds__(256) av_kernel(float* __restrict__ out)
{
    const int b  = blockIdx.z;
    const int qt = blockIdx.y;
    const int m0 = qt * 64;
    const int n0 = blockIdx.x * 64;

    const float* A = g_P + (size_t)b * SS * SS;  // [S,S]
    const float* V = g_V + (size_t)b * SS * FF;  // [S,F]
    float*       C = out + (size_t)b * SS * FF;

    __shared__ float As[16][64];
    __shared__ float Bs[16][64];

    const int tid = threadIdx.x;
    const int lr = tid >> 2;          // A: tile row
    const int lc = (tid & 3) * 4;     // A: k offset
    const int br = tid >> 4;          // B: k row (0..15)
    const int bc = (tid & 15) * 4;    // B: n offset
    const int ty = tid >> 4;
    const int tx = tid & 15;

    float acc[4][4] = {};
    const int kmax = (qt + 1) * 64;

    for (int k0 = 0; k0 < kmax; k0 += 16) {
        float4 a = *(const float4*)&A[(size_t)(m0 + lr) * SS + k0 + lc];
        float4 v = *(const float4*)&V[(size_t)(k0 + br) * FF + n0 + bc];
        As[lc + 0][lr] = a.x; As[lc + 1][lr] = a.y;
        As[lc + 2][lr] = a.z; As[lc + 3][lr] = a.w;
        *(float4*)&Bs[br][bc] = v;
        __syncthreads();
        #pragma unroll
        for (int k = 0; k < 16; ++k) {
            float4 af = *(const float4*)&As[k][ty * 4];
            float4 bf = *(const float4*)&Bs[k][tx * 4];
            acc[0][0] += af.x * bf.x; acc[0][1] += af.x * bf.y;
            acc[0][2] += af.x * bf.z; acc[0][3] += af.x * bf.w;
            acc[1][0] += af.y * bf.x; acc[1][1] += af.y * bf.y;
            acc[1][2] += af.y * bf.z; acc[1][3] += af.y * bf.w;
            acc[2][0] += af.z * bf.x; acc[2][1] += af.z * bf.y;
            acc[2][2] += af.z * bf.z; acc[2][3] += af.z * bf.w;
            acc[3][0] += af.w * bf.x; acc[3][1] += af.w * bf.y;
            acc[3][2] += af.w * bf.z; acc[3][3] += af.w * bf.w;
        }
        __syncthreads();
    }

    #pragma unroll
    for (int i = 0; i < 4; ++i) {
        float4 o = make_float4(acc[i][0], acc[i][1], acc[i][2], acc[i][3]);
        *(float4*)&C[(size_t)(m0 + ty * 4 + i) * FF + n0 + tx * 4] = o;
    }
}

extern "C" void kernel_launch(void* const* d_in, const int* in_sizes, int n_in,
                              void* d_out, int out_size)
{
    const float* x        = (const float*)d_in[0];
    // d_in[1] = attn_mask (exact causal tril, handled analytically)
    const int*   pad_mask = (const int*)d_in[2];
    const float* Wq = (const float*)d_in[3];
    const float* bq = (const float*)d_in[4];
    const float* Wk = (const float*)d_in[5];
    const float* bk = (const float*)d_in[6];
    const float* Wv = (const float*)d_in[7];
    const float* bv = (const float*)d_in[8];
    float* out = (float*)d_out;

    dim3 blk(256);
    qkv_kernel   <<<dim3(FF / 64, (BB * SS) / 64, 3), blk>>>(x, Wq, bq, Wk, bk, Wv, bv);
    scores_kernel<<<dim3(SS / 64, SS / 64, BB),       blk>>>(pad_mask);
    softmax_kernel<<<dim3(SS, BB),                    blk>>>();
    av_kernel    <<<dim3(FF / 64, SS / 64, BB),       blk>>>(out);
}

// round 4
// speedup vs baseline: 1.7200x; 1.7200x over previous
#include <cuda_runtime.h>
#include <cstdint>

#define BB 8
#define SS 2048
#define FF 1024
#define NEGV -1000000000.0f

// Scratch (allocation-free rule: __device__ globals)
__device__ float g_Q [BB * SS * FF];   // 64 MB
__device__ float g_K [BB * SS * FF];   // 64 MB
__device__ float g_Vt[BB * FF * SS];   // 64 MB  (V transposed: [b][f][s])
__device__ float g_P [BB * SS * SS];   // 128 MB (scores -> probs in place)

// Dynamic smem: two double-buffered stage buffers
//   buf0: A @0 (16KB), B @16K (16KB); buf1: A @32K, B @48K
// qkv V-transpose epilogue reuses [0, 128*132*4) after the pipeline drains.
extern __shared__ __align__(1024) char dsm[];
#define SMEM_BYTES (128 * 132 * 4)   // 67584 (>= 65536 pipeline need)

#define SW128(o) ((o) ^ (((o) >> 3) & 0x70))

static __device__ __forceinline__ uint32_t smem_u32(const void* p) {
    uint32_t a;
    asm("{ .reg .u64 t; cvta.to.shared.u64 t, %1; cvt.u32.u64 %0, t; }" : "=r"(a) : "l"(p));
    return a;
}

// Round-to-nearest tf32 (result is fp32 bit pattern, low 13 mantissa bits 0)
static __device__ __forceinline__ uint32_t f2tf(float x) {
    uint32_t r;
    asm("cvt.rna.tf32.f32 %0, %1;" : "=r"(r) : "f"(x));
    return r;
}
// Split fp32 vector (as u32 regs) into tf32 hi + tf32 lo
static __device__ __forceinline__ void split4(const uint32_t* f, uint32_t* hi, uint32_t* lo) {
    #pragma unroll
    for (int i = 0; i < 4; ++i) {
        float x = __uint_as_float(f[i]);
        hi[i] = f2tf(x);
        lo[i] = f2tf(x - __uint_as_float(hi[i]));
    }
}

// ---------------------------------------------------------------------------
// 3xTF32 mma.sync GEMM core: 128x128 block tile, K in chunks of 32.
// 256 threads = 8 warps in a 4(m) x 2(n) grid; warp tile 32x64.
// NT form: C[m,n] = sum_k A[m,k] * B[n,k]  (both K-contiguous rows).
// ---------------------------------------------------------------------------

static __device__ __forceinline__ void stage_chunk(
    const float* gA, int ldA, const float* gB, int ldB,
    uint32_t sA, uint32_t sB)
{
    const int t = threadIdx.x;
    #pragma unroll
    for (int i = 0; i < 4; ++i) {
        int s   = t + i * 256;          // 1024 16B segments per matrix
        int row = s >> 3;               // 0..127
        int seg = s & 7;                // 16B segment within 128B row
        uint32_t off = SW128(row * 128 + seg * 16);
        const float* pa = gA + (size_t)row * ldA + seg * 4;
        const float* pb = gB + (size_t)row * ldB + seg * 4;
        asm volatile("cp.async.cg.shared.global [%0], [%1], 16;"
                     :: "r"(sA + off), "l"(pa) : "memory");
        asm volatile("cp.async.cg.shared.global [%0], [%1], 16;"
                     :: "r"(sB + off), "l"(pb) : "memory");
    }
}

static __device__ __forceinline__ void mma_tf32(float* c, const uint32_t* a,
                                                uint32_t b0, uint32_t b1)
{
    asm volatile(
        "mma.sync.aligned.m16n8k8.row.col.f32.tf32.tf32.f32 "
        "{%0,%1,%2,%3}, {%4,%5,%6,%7}, {%8,%9}, {%0,%1,%2,%3};"
        : "+f"(c[0]), "+f"(c[1]), "+f"(c[2]), "+f"(c[3])
        : "r"(a[0]), "r"(a[1]), "r"(a[2]), "r"(a[3]), "r"(b0), "r"(b1));
}

static __device__ __forceinline__ void compute_chunk(
    uint32_t sA, uint32_t sB, float acc[2][8][4])
{
    const int lane = threadIdx.x & 31;
    const int w    = threadIdx.x >> 5;
    const int wm   = w & 3;             // warp m index (0..3) -> 32-row slab
    const int wn   = w >> 2;            // warp n index (0..1) -> 64-col slab
    const int r    = lane & 7;
    const int mid  = lane >> 3;         // ldmatrix matrix id (0..3)

    #pragma unroll
    for (int ki = 0; ki < 4; ++ki) {
        // A fragments + hi/lo split: one ldmatrix.x4 per 16-row m-frag
        uint32_t aH[2][4], aL[2][4];
        #pragma unroll
        for (int mi = 0; mi < 2; ++mi) {
            uint32_t aF[4];
            int row = wm * 32 + mi * 16 + (mid & 1) * 8 + r;
            int ks  = ki * 2 + (mid >> 1);
            uint32_t ad = sA + SW128(row * 128 + ks * 16);
            asm volatile("ldmatrix.sync.aligned.m8n8.x4.shared.b16 {%0,%1,%2,%3}, [%4];"
                : "=r"(aF[0]), "=r"(aF[1]), "=r"(aF[2]), "=r"(aF[3]) : "r"(ad));
            split4(aF, aH[mi], aL[mi]);
        }
        // B fragments per pair of n8 tiles, split, then 3 MMAs per (mi,j)
        #pragma unroll
        for (int pj = 0; pj < 4; ++pj) {
            uint32_t bF[4], bH[4], bL[4];
            int jj  = pj * 2 + (mid >> 1);
            int ks  = ki * 2 + (mid & 1);
            int row = wn * 64 + jj * 8 + r;
            uint32_t bd = sB + SW128(row * 128 + ks * 16);
            asm volatile("ldmatrix.sync.aligned.m8n8.x4.shared.b16 {%0,%1,%2,%3}, [%4];"
                : "=r"(bF[0]), "=r"(bF[1]), "=r"(bF[2]), "=r"(bF[3]) : "r"(bd));
            split4(bF, bH, bL);
            #pragma unroll
            for (int mi = 0; mi < 2; ++mi) {
                float* c0 = acc[mi][pj * 2 + 0];
                float* c1 = acc[mi][pj * 2 + 1];
                mma_tf32(c0, aH[mi], bH[0], bH[1]);   // hi*hi
                mma_tf32(c0, aH[mi], bL[0], bL[1]);   // hi*lo
                mma_tf32(c0, aL[mi], bH[0], bH[1]);   // lo*hi
                mma_tf32(c1, aH[mi], bH[2], bH[3]);
                mma_tf32(c1, aH[mi], bL[2], bL[3]);
                mma_tf32(c1, aL[mi], bH[2], bH[3]);
            }
        }
    }
}

static __device__ __forceinline__ void gemm(
    const float* gA, int ldA, const float* gB, int ldB,
    int NC, float acc[2][8][4])
{
    const uint32_t sb = smem_u32(dsm);
    stage_chunk(gA, ldA, gB, ldB, sb, sb + 16384);
    asm volatile("cp.async.commit_group;" ::: "memory");
    for (int c = 0; c < NC; ++c) {
        if (c + 1 < NC) {
            uint32_t nbo = sb + ((c + 1) & 1) * 32768;
            stage_chunk(gA + (size_t)(c + 1) * 32, ldA,
                        gB + (size_t)(c + 1) * 32, ldB, nbo, nbo + 16384);
            asm volatile("cp.async.commit_group;" ::: "memory");
            asm volatile("cp.async.wait_group 1;" ::: "memory");
        } else {
            asm volatile("cp.async.wait_group 0;" ::: "memory");
        }
        __syncthreads();
        uint32_t cbo = sb + (c & 1) * 32768;
        compute_chunk(cbo, cbo + 16384, acc);
        __syncthreads();
    }
}

// Epilogue coords: row_base = wm*32 + mi*16 + (lane>>2); col = wn*64 + j*8 + (lane&3)*2
//   acc[mi][j] = {c(row,col), c(row,col+1), c(row+8,col), c(row+8,col+1)}

// ---------------------------------------------------------------------------
// Kernel 1: QKV projection; z==2 writes transposed Vt via smem transpose.
// ---------------------------------------------------------------------------
__global__ void __launch_bounds__(256) qkv_kernel(
    const float* __restrict__ x,
    const float* __restrict__ Wq, const float* __restrict__ bq,
    const float* __restrict__ Wk, const float* __restrict__ bk,
    const float* __restrict__ Wv, const float* __restrict__ bv)
{
    const int z = blockIdx.z;
    const float* W; const float* bias;
    if (z == 0)      { W = Wq; bias = bq; }
    else if (z == 1) { W = Wk; bias = bk; }
    else             { W = Wv; bias = bv; }

    const int m0 = blockIdx.y * 128;
    const int n0 = blockIdx.x * 128;

    float acc[2][8][4] = {};
    gemm(x + (size_t)m0 * FF, FF, W + (size_t)n0 * FF, FF, FF / 32, acc);

    const int lane = threadIdx.x & 31;
    const int w    = threadIdx.x >> 5;
    const int wm = w & 3, wn = w >> 2;
    const int g = lane >> 2, tq = lane & 3;

    if (z < 2) {
        float* C = (z == 0 ? g_Q : g_K);
        #pragma unroll
        for (int mi = 0; mi < 2; ++mi) {
            int row = m0 + wm * 32 + mi * 16 + g;
            #pragma unroll
            for (int j = 0; j < 8; ++j) {
                int col = n0 + wn * 64 + j * 8 + tq * 2;
                float2 b2 = *(const float2*)&bias[col];
                float2 o0 = { acc[mi][j][0] + b2.x, acc[mi][j][1] + b2.y };
                float2 o1 = { acc[mi][j][2] + b2.x, acc[mi][j][3] + b2.y };
                *(float2*)&C[(size_t)row * FF + col]       = o0;
                *(float2*)&C[(size_t)(row + 8) * FF + col] = o1;
            }
        }
    } else {
        float* st = (float*)dsm;   // [128][132] transpose staging
        #pragma unroll
        for (int mi = 0; mi < 2; ++mi) {
            int row = wm * 32 + mi * 16 + g;
            #pragma unroll
            for (int j = 0; j < 8; ++j) {
                int col = wn * 64 + j * 8 + tq * 2;
                float2 b2 = *(const float2*)&bias[n0 + col];
                st[(size_t)row * 132 + col]           = acc[mi][j][0] + b2.x;
                st[(size_t)row * 132 + col + 1]       = acc[mi][j][1] + b2.y;
                st[(size_t)(row + 8) * 132 + col]     = acc[mi][j][2] + b2.x;
                st[(size_t)(row + 8) * 132 + col + 1] = acc[mi][j][3] + b2.y;
            }
        }
        __syncthreads();
        const int f  = threadIdx.x & 127;
        const int sh = threadIdx.x >> 7;
        const int b  = m0 >> 11;           // tile never straddles a batch
        const int s0 = m0 & (SS - 1);
        float* vrow = g_Vt + ((size_t)b * FF + (n0 + f)) * SS + s0 + sh * 64;
        #pragma unroll
        for (int jj = 0; jj < 16; ++jj) {
            float4 o;
            o.x = st[(size_t)(sh * 64 + 4 * jj + 0) * 132 + f];
            o.y = st[(size_t)(sh * 64 + 4 * jj + 1) * 132 + f];
            o.z = st[(size_t)(sh * 64 + 4 * jj + 2) * 132 + f];
            o.w = st[(size_t)(sh * 64 + 4 * jj + 3) * 132 + f];
            *(float4*)&vrow[4 * jj] = o;
        }
    }
}

// ---------------------------------------------------------------------------
// Kernel 2: scores = scale * Q @ K^T, causal tile skip, masks fused.
// ---------------------------------------------------------------------------
__global__ void __launch_bounds__(256) scores_kernel(const int* __restrict__ pad_mask)
{
    const int kt = blockIdx.x, qt = blockIdx.y, b = blockIdx.z;
    if (kt > qt) return;
    const int m0 = qt * 128, n0 = kt * 128;

    float acc[2][8][4] = {};
    gemm(g_Q + ((size_t)b * SS + m0) * FF, FF,
         g_K + ((size_t)b * SS + n0) * FF, FF, FF / 32, acc);

    const int lane = threadIdx.x & 31;
    const int w    = threadIdx.x >> 5;
    const int wm = w & 3, wn = w >> 2;
    const int g = lane >> 2, tq = lane & 3;

    float* P = g_P + (size_t)b * SS * SS;
    const int* pm = pad_mask + (size_t)b * SS;
    const float scale = 0.03125f;  // 1/sqrt(1024)

    #pragma unroll
    for (int mi = 0; mi < 2; ++mi) {
        int q0 = m0 + wm * 32 + mi * 16 + g;
        #pragma unroll
        for (int j = 0; j < 8; ++j) {
            int col = n0 + wn * 64 + j * 8 + tq * 2;
            int2 p2 = *(const int2*)&pm[col];
            float2 o0, o1;
            o0.x = (p2.x == 0 || col     > q0) ? NEGV : acc[mi][j][0] * scale;
            o0.y = (p2.y == 0 || col + 1 > q0) ? NEGV : acc[mi][j][1] * scale;
            int q1 = q0 + 8;
            o1.x = (p2.x == 0 || col     > q1) ? NEGV : acc[mi][j][2] * scale;
            o1.y = (p2.y == 0 || col + 1 > q1) ? NEGV : acc[mi][j][3] * scale;
            *(float2*)&P[(size_t)q0 * SS + col] = o0;
            *(float2*)&P[(size_t)q1 * SS + col] = o1;
        }
    }
}

// ---------------------------------------------------------------------------
// Kernel 3: row softmax over [0, q], zero-fill to the 128-tile boundary.
// ---------------------------------------------------------------------------
__global__ void __launch_bounds__(256) softmax_kernel()
{
    const int b = blockIdx.y;
    const int q = blockIdx.x;
    float* row = g_P + (size_t)b * SS * SS + (size_t)q * SS;
    const int len = q + 1;
    const int tid = threadIdx.x;

    __shared__ float red[32];

    float vals[8];
    float m = -3.4e38f;
    #pragma unroll
    for (int i = 0; i < 8; ++i) {
        int k = tid + i * 256;
        vals[i] = (k < len) ? row[k] : -3.4e38f;
        m = fmaxf(m, vals[i]);
    }
    #pragma unroll
    for (int o = 16; o > 0; o >>= 1) m = fmaxf(m, __shfl_xor_sync(0xffffffffu, m, o));
    if ((tid & 31) == 0) red[tid >> 5] = m;
    __syncthreads();
    m = red[tid & 7];
    #pragma unroll
    for (int o = 4; o > 0; o >>= 1) m = fmaxf(m, __shfl_xor_sync(0xffffffffu, m, o));
    __syncthreads();

    float s = 0.f;
    #pragma unroll
    for (int i = 0; i < 8; ++i) {
        vals[i] = __expf(vals[i] - m);
        s += vals[i];
    }
    #pragma unroll
    for (int o = 16; o > 0; o >>= 1) s += __shfl_xor_sync(0xffffffffu, s, o);
    if ((tid & 31) == 0) red[tid >> 5] = s;
    __syncthreads();
    s = red[tid & 7];
    #pragma unroll
    for (int o = 4; o > 0; o >>= 1) s += __shfl_xor_sync(0xffffffffu, s, o);

    const float inv = 1.0f / s;
    #pragma unroll
    for (int i = 0; i < 8; ++i) {
        int k = tid + i * 256;
        if (k < len) row[k] = vals[i] * inv;
    }
    const int kEnd = ((q >> 7) + 1) << 7;   // 128-tile boundary
    for (int k = len + tid; k < kEnd; k += 256) row[k] = 0.f;
}

// ---------------------------------------------------------------------------
// Kernel 4: out = P @ Vt^T, K truncated at the causal 128-boundary.
// ---------------------------------------------------------------------------
__global__ void __launch_bounds__(256) av_kernel(float* __restrict__ out)
{
    const int n0 = blockIdx.x * 128, qt = blockIdx.y, b = blockIdx.z;
    const int m0 = qt * 128;

    float acc[2][8][4] = {};
    gemm(g_P  + ((size_t)b * SS + m0) * SS, SS,
         g_Vt + ((size_t)b * FF + n0) * SS, SS,
         (qt + 1) * 4, acc);

    const int lane = threadIdx.x & 31;
    const int w    = threadIdx.x >> 5;
    const int wm = w & 3, wn = w >> 2;
    const int g = lane >> 2, tq = lane & 3;

    float* C = out + (size_t)b * SS * FF;
    #pragma unroll
    for (int mi = 0; mi < 2; ++mi) {
        int row = m0 + wm * 32 + mi * 16 + g;
        #pragma unroll
        for (int j = 0; j < 8; ++j) {
            int col = n0 + wn * 64 + j * 8 + tq * 2;
            float2 o0 = { acc[mi][j][0], acc[mi][j][1] };
            float2 o1 = { acc[mi][j][2], acc[mi][j][3] };
            *(float2*)&C[(size_t)row * FF + col]       = o0;
            *(float2*)&C[(size_t)(row + 8) * FF + col] = o1;
        }
    }
}

extern "C" void kernel_launch(void* const* d_in, const int* in_sizes, int n_in,
                              void* d_out, int out_size)
{
    const float* x        = (const float*)d_in[0];
    // d_in[1] = attn_mask (exact causal tril, handled analytically)
    const int*   pad_mask = (const int*)d_in[2];
    const float* Wq = (const float*)d_in[3];
    const float* bq = (const float*)d_in[4];
    const float* Wk = (const float*)d_in[5];
    const float* bk = (const float*)d_in[6];
    const float* Wv = (const float*)d_in[7];
    const float* bv = (const float*)d_in[8];
    float* out = (float*)d_out;

    cudaFuncSetAttribute(qkv_kernel,    cudaFuncAttributeMaxDynamicSharedMemorySize, SMEM_BYTES);
    cudaFuncSetAttribute(scores_kernel, cudaFuncAttributeMaxDynamicSharedMemorySize, SMEM_BYTES);
    cudaFuncSetAttribute(av_kernel,     cudaFuncAttributeMaxDynamicSharedMemorySize, SMEM_BYTES);

    dim3 blk(256);
    qkv_kernel   <<<dim3(FF / 128, (BB * SS) / 128, 3), blk, SMEM_BYTES>>>(x, Wq, bq, Wk, bk, Wv, bv);
    scores_kernel<<<dim3(SS / 128, SS / 128, BB),        blk, SMEM_BYTES>>>(pad_mask);
    softmax_kernel<<<dim3(SS, BB),                       blk>>>();
    av_kernel    <<<dim3(FF / 128, SS / 128, BB),        blk, SMEM_BYTES>>>(out);
}

// round 5
// speedup vs baseline: 1.9256x; 1.1195x over previous
#include <cuda_runtime.h>
#include <cstdint>

#define BB 8
#define SS 2048
#define FF 1024
#define NEGV -1000000000.0f

// Persistent hi/lo split operands (allocation-free rule: __device__ globals)
__device__ float g_Xh [BB * SS * FF];
__device__ float g_Xl [BB * SS * FF];
__device__ float g_Wh [3 * FF * FF];
__device__ float g_Wl [3 * FF * FF];
__device__ float g_Qh [BB * SS * FF];
__device__ float g_Ql [BB * SS * FF];
__device__ float g_Kh [BB * SS * FF];
__device__ float g_Kl [BB * SS * FF];
__device__ float g_Vth[BB * FF * SS];   // V transposed [b][f][s]
__device__ float g_Vtl[BB * FF * SS];
__device__ float g_S  [BB * SS * SS];   // raw masked scores
__device__ float g_Ph [BB * SS * SS];   // probs hi/lo
__device__ float g_Pl [BB * SS * SS];

// Dynamic smem: double-buffered 4-tile chunks.
//   buffer = [Ah 16K][Al 16K][Bh 16K][Bl 16K] = 64K; two buffers = 128K.
// qkv V-transpose epilogue reuses [0, 128*132*4) after pipeline drains.
extern __shared__ __align__(1024) char dsm[];
#define BUF_STRIDE 65536u
#define OFF_AL 16384u
#define OFF_BH 32768u
#define OFF_BL 49152u
#define SMEM_BYTES 131072

#define SW128(o) ((o) ^ (((o) >> 3) & 0x70))

static __device__ __forceinline__ uint32_t smem_u32(const void* p) {
    uint32_t a;
    asm("{ .reg .u64 t; cvta.to.shared.u64 t, %1; cvt.u32.u64 %0, t; }" : "=r"(a) : "l"(p));
    return a;
}
static __device__ __forceinline__ uint32_t f2tf(float x) {
    uint32_t r;
    asm("cvt.rna.tf32.f32 %0, %1;" : "=r"(r) : "f"(x));
    return r;
}
static __device__ __forceinline__ void split_store(
    float* __restrict__ hi, float* __restrict__ lo, size_t idx, float v)
{
    float h = __uint_as_float(f2tf(v));
    hi[idx] = h;
    lo[idx] = __uint_as_float(f2tf(v - h));
}

// ---------------------------------------------------------------------------
// 3xTF32 GEMM core on pre-split operands. 128x128 tile, K chunks of 32.
// 256 threads = 8 warps, 4(m) x 2(n); warp tile 32x64.
// Inner loop is pure ldmatrix + mma (no cvt).
// ---------------------------------------------------------------------------

static __device__ __forceinline__ void stage4(
    const float* gAh, const float* gAl, int ldA,
    const float* gBh, const float* gBl, int ldB, uint32_t sbuf)
{
    const int t = threadIdx.x;
    #pragma unroll
    for (int i = 0; i < 4; ++i) {
        int s   = t + i * 256;          // 1024 16B segments per tile
        int row = s >> 3;
        int seg = s & 7;
        uint32_t off = SW128(row * 128 + seg * 16);
        const float* pah = gAh + (size_t)row * ldA + seg * 4;
        const float* pal = gAl + (size_t)row * ldA + seg * 4;
        const float* pbh = gBh + (size_t)row * ldB + seg * 4;
        const float* pbl = gBl + (size_t)row * ldB + seg * 4;
        asm volatile("cp.async.cg.shared.global [%0], [%1], 16;" :: "r"(sbuf + off),          "l"(pah) : "memory");
        asm volatile("cp.async.cg.shared.global [%0], [%1], 16;" :: "r"(sbuf + OFF_AL + off), "l"(pal) : "memory");
        asm volatile("cp.async.cg.shared.global [%0], [%1], 16;" :: "r"(sbuf + OFF_BH + off), "l"(pbh) : "memory");
        asm volatile("cp.async.cg.shared.global [%0], [%1], 16;" :: "r"(sbuf + OFF_BL + off), "l"(pbl) : "memory");
    }
}

static __device__ __forceinline__ void mma_tf32(float* c, const uint32_t* a,
                                                uint32_t b0, uint32_t b1)
{
    asm volatile(
        "mma.sync.aligned.m16n8k8.row.col.f32.tf32.tf32.f32 "
        "{%0,%1,%2,%3}, {%4,%5,%6,%7}, {%8,%9}, {%0,%1,%2,%3};"
        : "+f"(c[0]), "+f"(c[1]), "+f"(c[2]), "+f"(c[3])
        : "r"(a[0]), "r"(a[1]), "r"(a[2]), "r"(a[3]), "r"(b0), "r"(b1));
}

#define LDSM4(dst, addr) \
    asm volatile("ldmatrix.sync.aligned.m8n8.x4.shared.b16 {%0,%1,%2,%3}, [%4];" \
        : "=r"((dst)[0]), "=r"((dst)[1]), "=r"((dst)[2]), "=r"((dst)[3]) : "r"(addr))

static __device__ __forceinline__ void compute_chunk(uint32_t sbuf, float acc[2][8][4])
{
    const int lane = threadIdx.x & 31;
    const int w    = threadIdx.x >> 5;
    const int wm   = w & 3;
    const int wn   = w >> 2;
    const int r    = lane & 7;
    const int mid  = lane >> 3;

    #pragma unroll
    for (int ki = 0; ki < 4; ++ki) {
        uint32_t aH[2][4], aL[2][4];
        #pragma unroll
        for (int mi = 0; mi < 2; ++mi) {
            int row = wm * 32 + mi * 16 + (mid & 1) * 8 + r;
            int ks  = ki * 2 + (mid >> 1);
            uint32_t off = SW128(row * 128 + ks * 16);
            LDSM4(aH[mi], sbuf + off);
            LDSM4(aL[mi], sbuf + OFF_AL + off);
        }
        #pragma unroll
        for (int pj = 0; pj < 4; ++pj) {
            uint32_t bH[4], bL[4];
            int jj  = pj * 2 + (mid >> 1);
            int ks  = ki * 2 + (mid & 1);
            int row = wn * 64 + jj * 8 + r;
            uint32_t off = SW128(row * 128 + ks * 16);
            LDSM4(bH, sbuf + OFF_BH + off);
            LDSM4(bL, sbuf + OFF_BL + off);
            #pragma unroll
            for (int mi = 0; mi < 2; ++mi) {
                float* c0 = acc[mi][pj * 2 + 0];
                float* c1 = acc[mi][pj * 2 + 1];
                mma_tf32(c0, aH[mi], bH[0], bH[1]);
                mma_tf32(c0, aH[mi], bL[0], bL[1]);
                mma_tf32(c0, aL[mi], bH[0], bH[1]);
                mma_tf32(c1, aH[mi], bH[2], bH[3]);
                mma_tf32(c1, aH[mi], bL[2], bL[3]);
                mma_tf32(c1, aL[mi], bH[2], bH[3]);
            }
        }
    }
}

static __device__ __forceinline__ void gemm(
    const float* gAh, const float* gAl, int ldA,
    const float* gBh, const float* gBl, int ldB,
    int NC, float acc[2][8][4])
{
    const uint32_t sb = smem_u32(dsm);
    stage4(gAh, gAl, ldA, gBh, gBl, ldB, sb);
    asm volatile("cp.async.commit_group;" ::: "memory");
    for (int c = 0; c < NC; ++c) {
        if (c + 1 < NC) {
            uint32_t nbo = sb + ((c + 1) & 1) * BUF_STRIDE;
            stage4(gAh + (size_t)(c + 1) * 32, gAl + (size_t)(c + 1) * 32, ldA,
                   gBh + (size_t)(c + 1) * 32, gBl + (size_t)(c + 1) * 32, ldB, nbo);
            asm volatile("cp.async.commit_group;" ::: "memory");
            asm volatile("cp.async.wait_group 1;" ::: "memory");
        } else {
            asm volatile("cp.async.wait_group 0;" ::: "memory");
        }
        __syncthreads();
        compute_chunk(sb + (c & 1) * BUF_STRIDE, acc);
        __syncthreads();
    }
}

// Epilogue coords: row = wm*32 + mi*16 + (lane>>2) (+8); col = wn*64 + j*8 + (lane&3)*2 (+1)
//   acc[mi][j] = {c(row,col), c(row,col+1), c(row+8,col), c(row+8,col+1)}

// ---------------------------------------------------------------------------
// Kernel 0: elementwise hi/lo split (float4 vectorized)
// ---------------------------------------------------------------------------
__global__ void __launch_bounds__(256) split_kernel(
    const float* __restrict__ src, float* __restrict__ hi, float* __restrict__ lo, int n4)
{
    int i = blockIdx.x * blockDim.x + threadIdx.x;
    if (i >= n4) return;
    float4 v = ((const float4*)src)[i];
    float4 h, l;
    h.x = __uint_as_float(f2tf(v.x)); l.x = __uint_as_float(f2tf(v.x - h.x));
    h.y = __uint_as_float(f2tf(v.y)); l.y = __uint_as_float(f2tf(v.y - h.y));
    h.z = __uint_as_float(f2tf(v.z)); l.z = __uint_as_float(f2tf(v.z - h.z));
    h.w = __uint_as_float(f2tf(v.w)); l.w = __uint_as_float(f2tf(v.w - h.w));
    ((float4*)hi)[i] = h;
    ((float4*)lo)[i] = l;
}

// ---------------------------------------------------------------------------
// Kernel 1: QKV projection; outputs split (Qh,Ql)/(Kh,Kl)/(Vth,Vtl).
// ---------------------------------------------------------------------------
__global__ void __launch_bounds__(256) qkv_kernel(
    const float* __restrict__ bq, const float* __restrict__ bk, const float* __restrict__ bv)
{
    const int z = blockIdx.z;
    const float* bias = (z == 0) ? bq : (z == 1) ? bk : bv;
    const int m0 = blockIdx.y * 128;
    const int n0 = blockIdx.x * 128;

    float acc[2][8][4] = {};
    gemm(g_Xh + (size_t)m0 * FF, g_Xl + (size_t)m0 * FF, FF,
         g_Wh + (size_t)z * FF * FF + (size_t)n0 * FF,
         g_Wl + (size_t)z * FF * FF + (size_t)n0 * FF, FF, FF / 32, acc);

    const int lane = threadIdx.x & 31;
    const int w    = threadIdx.x >> 5;
    const int wm = w & 3, wn = w >> 2;
    const int g = lane >> 2, tq = lane & 3;

    if (z < 2) {
        float* H = (z == 0 ? g_Qh : g_Kh);
        float* L = (z == 0 ? g_Ql : g_Kl);
        #pragma unroll
        for (int mi = 0; mi < 2; ++mi) {
            int row = m0 + wm * 32 + mi * 16 + g;
            #pragma unroll
            for (int j = 0; j < 8; ++j) {
                int col = n0 + wn * 64 + j * 8 + tq * 2;
                float2 b2 = *(const float2*)&bias[col];
                split_store(H, L, (size_t)row * FF + col,           acc[mi][j][0] + b2.x);
                split_store(H, L, (size_t)row * FF + col + 1,       acc[mi][j][1] + b2.y);
                split_store(H, L, (size_t)(row + 8) * FF + col,     acc[mi][j][2] + b2.x);
                split_store(H, L, (size_t)(row + 8) * FF + col + 1, acc[mi][j][3] + b2.y);
            }
        }
    } else {
        float* st = (float*)dsm;   // [128][132] fp32 transpose staging
        #pragma unroll
        for (int mi = 0; mi < 2; ++mi) {
            int row = wm * 32 + mi * 16 + g;
            #pragma unroll
            for (int j = 0; j < 8; ++j) {
                int col = wn * 64 + j * 8 + tq * 2;
                float2 b2 = *(const float2*)&bias[n0 + col];
                st[(size_t)row * 132 + col]           = acc[mi][j][0] + b2.x;
                st[(size_t)row * 132 + col + 1]       = acc[mi][j][1] + b2.y;
                st[(size_t)(row + 8) * 132 + col]     = acc[mi][j][2] + b2.x;
                st[(size_t)(row + 8) * 132 + col + 1] = acc[mi][j][3] + b2.y;
            }
        }
        __syncthreads();
        const int f  = threadIdx.x & 127;
        const int sh = threadIdx.x >> 7;
        const int b  = m0 >> 11;           // tile never straddles a batch
        const int s0 = m0 & (SS - 1);
        size_t base = ((size_t)b * FF + (n0 + f)) * SS + s0 + sh * 64;
        #pragma unroll
        for (int jj = 0; jj < 64; ++jj) {
            float v = st[(size_t)(sh * 64 + jj) * 132 + f];
            split_store(g_Vth, g_Vtl, base + jj, v);
        }
    }
}

// ---------------------------------------------------------------------------
// Kernel 2: scores = scale * Q @ K^T, causal tile skip, masks fused -> g_S.
// ---------------------------------------------------------------------------
__global__ void __launch_bounds__(256) scores_kernel(const int* __restrict__ pad_mask)
{
    const int kt = blockIdx.x, qt = blockIdx.y, b = blockIdx.z;
    if (kt > qt) return;
    const int m0 = qt * 128, n0 = kt * 128;

    float acc[2][8][4] = {};
    gemm(g_Qh + ((size_t)b * SS + m0) * FF, g_Ql + ((size_t)b * SS + m0) * FF, FF,
         g_Kh + ((size_t)b * SS + n0) * FF, g_Kl + ((size_t)b * SS + n0) * FF, FF,
         FF / 32, acc);

    const int lane = threadIdx.x & 31;
    const int w    = threadIdx.x >> 5;
    const int wm = w & 3, wn = w >> 2;
    const int g = lane >> 2, tq = lane & 3;

    float* P = g_S + (size_t)b * SS * SS;
    const int* pm = pad_mask + (size_t)b * SS;
    const float scale = 0.03125f;  // 1/sqrt(1024)

    #pragma unroll
    for (int mi = 0; mi < 2; ++mi) {
        int q0 = m0 + wm * 32 + mi * 16 + g;
        #pragma unroll
        for (int j = 0; j < 8; ++j) {
            int col = n0 + wn * 64 + j * 8 + tq * 2;
            int2 p2 = *(const int2*)&pm[col];
            float2 o0, o1;
            o0.x = (p2.x == 0 || col     > q0) ? NEGV : acc[mi][j][0] * scale;
            o0.y = (p2.y == 0 || col + 1 > q0) ? NEGV : acc[mi][j][1] * scale;
            int q1 = q0 + 8;
            o1.x = (p2.x == 0 || col     > q1) ? NEGV : acc[mi][j][2] * scale;
            o1.y = (p2.y == 0 || col + 1 > q1) ? NEGV : acc[mi][j][3] * scale;
            *(float2*)&P[(size_t)q0 * SS + col] = o0;
            *(float2*)&P[(size_t)q1 * SS + col] = o1;
        }
    }
}

// ---------------------------------------------------------------------------
// Kernel 3: row softmax over [0, q]; writes split probs (Ph,Pl); zero-fills
// to the 128-tile boundary.
// ---------------------------------------------------------------------------
__global__ void __launch_bounds__(256) softmax_kernel()
{
    const int b = blockIdx.y;
    const int q = blockIdx.x;
    const size_t ro = (size_t)b * SS * SS + (size_t)q * SS;
    const float* row = g_S + ro;
    const int len = q + 1;
    const int tid = threadIdx.x;

    __shared__ float red[32];

    float vals[8];
    float m = -3.4e38f;
    #pragma unroll
    for (int i = 0; i < 8; ++i) {
        int k = tid + i * 256;
        vals[i] = (k < len) ? row[k] : -3.4e38f;
        m = fmaxf(m, vals[i]);
    }
    #pragma unroll
    for (int o = 16; o > 0; o >>= 1) m = fmaxf(m, __shfl_xor_sync(0xffffffffu, m, o));
    if ((tid & 31) == 0) red[tid >> 5] = m;
    __syncthreads();
    m = red[tid & 7];
    #pragma unroll
    for (int o = 4; o > 0; o >>= 1) m = fmaxf(m, __shfl_xor_sync(0xffffffffu, m, o));
    __syncthreads();

    float s = 0.f;
    #pragma unroll
    for (int i = 0; i < 8; ++i) {
        vals[i] = __expf(vals[i] - m);
        s += vals[i];
    }
    #pragma unroll
    for (int o = 16; o > 0; o >>= 1) s += __shfl_xor_sync(0xffffffffu, s, o);
    if ((tid & 31) == 0) red[tid >> 5] = s;
    __syncthreads();
    s = red[tid & 7];
    #pragma unroll
    for (int o = 4; o > 0; o >>= 1) s += __shfl_xor_sync(0xffffffffu, s, o);

    const float inv = 1.0f / s;
    #pragma unroll
    for (int i = 0; i < 8; ++i) {
        int k = tid + i * 256;
        if (k < len) split_store(g_Ph, g_Pl, ro + k, vals[i] * inv);
    }
    const int kEnd = ((q >> 7) + 1) << 7;
    for (int k = len + tid; k < kEnd; k += 256) {
        g_Ph[ro + k] = 0.f;
        g_Pl[ro + k] = 0.f;
    }
}

// ---------------------------------------------------------------------------
// Kernel 4: out = P @ Vt^T, K truncated at the causal 128-boundary.
// ---------------------------------------------------------------------------
__global__ void __launch_bounds__(256) av_kernel(float* __restrict__ out)
{
    const int n0 = blockIdx.x * 128, qt = blockIdx.y, b = blockIdx.z;
    const int m0 = qt * 128;

    float acc[2][8][4] = {};
    gemm(g_Ph  + ((size_t)b * SS + m0) * SS, g_Pl  + ((size_t)b * SS + m0) * SS, SS,
         g_Vth + ((size_t)b * FF + n0) * SS, g_Vtl + ((size_t)b * FF + n0) * SS, SS,
         (qt + 1) * 4, acc);

    const int lane = threadIdx.x & 31;
    const int w    = threadIdx.x >> 5;
    const int wm = w & 3, wn = w >> 2;
    const int g = lane >> 2, tq = lane & 3;

    float* C = out + (size_t)b * SS * FF;
    #pragma unroll
    for (int mi = 0; mi < 2; ++mi) {
        int row = m0 + wm * 32 + mi * 16 + g;
        #pragma unroll
        for (int j = 0; j < 8; ++j) {
            int col = n0 + wn * 64 + j * 8 + tq * 2;
            float2 o0 = { acc[mi][j][0], acc[mi][j][1] };
            float2 o1 = { acc[mi][j][2], acc[mi][j][3] };
            *(float2*)&C[(size_t)row * FF + col]       = o0;
            *(float2*)&C[(size_t)(row + 8) * FF + col] = o1;
        }
    }
}

extern "C" void kernel_launch(void* const* d_in, const int* in_sizes, int n_in,
                              void* d_out, int out_size)
{
    const float* x        = (const float*)d_in[0];
    // d_in[1] = attn_mask (exact causal tril, handled analytically)
    const int*   pad_mask = (const int*)d_in[2];
    const float* Wq = (const float*)d_in[3];
    const float* bq = (const float*)d_in[4];
    const float* Wk = (const float*)d_in[5];
    const float* bk = (const float*)d_in[6];
    const float* Wv = (const float*)d_in[7];
    const float* bv = (const float*)d_in[8];
    float* out = (float*)d_out;

    static float* p_Xh = nullptr;
    float *xh, *xl, *wh, *wl;
    cudaGetSymbolAddress((void**)&xh, g_Xh);
    cudaGetSymbolAddress((void**)&xl, g_Xl);
    cudaGetSymbolAddress((void**)&wh, g_Wh);
    cudaGetSymbolAddress((void**)&wl, g_Wl);
    (void)p_Xh;

    cudaFuncSetAttribute(qkv_kernel,    cudaFuncAttributeMaxDynamicSharedMemorySize, SMEM_BYTES);
    cudaFuncSetAttribute(scores_kernel, cudaFuncAttributeMaxDynamicSharedMemorySize, SMEM_BYTES);
    cudaFuncSetAttribute(av_kernel,     cudaFuncAttributeMaxDynamicSharedMemorySize, SMEM_BYTES);

    dim3 blk(256);
    const int nx4 = BB * SS * FF / 4;
    const int nw4 = FF * FF / 4;
    split_kernel<<<(nx4 + 255) / 256, blk>>>(x,  xh, xl, nx4);
    split_kernel<<<(nw4 + 255) / 256, blk>>>(Wq, wh,              wl,              nw4);
    split_kernel<<<(nw4 + 255) / 256, blk>>>(Wk, wh + FF * FF,    wl + FF * FF,    nw4);
    split_kernel<<<(nw4 + 255) / 256, blk>>>(Wv, wh + 2 * FF * FF, wl + 2 * FF * FF, nw4);

    qkv_kernel   <<<dim3(FF / 128, (BB * SS) / 128, 3), blk, SMEM_BYTES>>>(bq, bk, bv);
    scores_kernel<<<dim3(SS / 128, SS / 128, BB),        blk, SMEM_BYTES>>>(pad_mask);
    softmax_kernel<<<dim3(SS, BB),                       blk>>>();
    av_kernel    <<<dim3(FF / 128, SS / 128, BB),        blk, SMEM_BYTES>>>(out);
}